// round 15
// baseline (speedup 1.0000x reference)
#include <cuda_runtime.h>
#include <cuda_bf16.h>
#include <cstdint>

#define FULL_MASK 0xFFFFFFFFu
#define TAGS 32
#define START 30
#define STOP 31
#define GOLD_BLOCKS 128

__device__ float g_fwd[2048];
__device__ float g_gold[2048];
__device__ int   g_count = 0;

typedef unsigned long long ull;

// ---- packed fp32x2 helpers (Blackwell FFMA2 path, full fp32 precision) ----
__device__ __forceinline__ ull pack2(float lo, float hi) {
    ull r; asm("mov.b64 %0, {%1, %2};" : "=l"(r) : "f"(lo), "f"(hi)); return r;
}
__device__ __forceinline__ void unpack2(float& lo, float& hi, ull v) {
    asm("mov.b64 {%0, %1}, %2;" : "=f"(lo), "=f"(hi) : "l"(v));
}
__device__ __forceinline__ ull fma2(ull a, ull b, ull c) {
    ull r; asm("fma.rn.f32x2 %0, %1, %2, %3;" : "=l"(r) : "l"(a), "l"(b), "l"(c)); return r;
}
__device__ __forceinline__ ull mul2(ull a, ull b) {
    ull r; asm("mul.rn.f32x2 %0, %1, %2;" : "=l"(r) : "l"(a), "l"(b)); return r;
}
__device__ __forceinline__ ull add2(ull a, ull b) {
    ull r; asm("add.rn.f32x2 %0, %1, %2;" : "=l"(r) : "l"(a), "l"(b)); return r;
}
__device__ __forceinline__ void lds_v2u64(ull& a, ull& b, uint32_t addr) {
    asm volatile("ld.shared.v2.u64 {%0, %1}, [%2];" : "=l"(a), "=l"(b) : "r"(addr));
}
__device__ __forceinline__ void sts16(uint32_t addr, uint16_t v) {
    asm volatile("st.shared.b16 [%0], %1;" :: "r"(addr), "h"(v) : "memory");
}
__device__ __forceinline__ uint16_t f32_to_bf16(float f) {
    uint16_t h; asm("cvt.rn.bf16.f32 %0, %1;" : "=h"(h) : "f"(f)); return h;
}
__device__ __forceinline__ void split_u64(uint32_t& lo, uint32_t& hi, ull v) {
    asm("mov.b64 {%0, %1}, %2;" : "=r"(lo), "=r"(hi) : "l"(v));
}
// bf16x2 word -> f32x2 operand (bf16 is truncated fp32: shift/mask only)
__device__ __forceinline__ ull bf2f(uint32_t w) {
    uint32_t lo = w << 16;
    uint32_t hi = w & 0xFFFF0000u;
    ull r; asm("mov.b64 %0, {%1, %2};" : "=l"(r) : "r"(lo), "r"(hi));
    return r;
}

// bf16 broadcast matvec: 4x LDS.v2.u64 (64B row, broadcast) -> 16 fma2 fp32
__device__ __forceinline__ float matvec32_bf16(uint32_t base, const ull* Ep) {
    ull a0, b0, a1, b1, a2, b2, a3, b3;
    lds_v2u64(a0, b0, base +  0);
    lds_v2u64(a1, b1, base + 16);
    lds_v2u64(a2, b2, base + 32);
    lds_v2u64(a3, b3, base + 48);
    uint32_t w[16];
    split_u64(w[0],  w[1],  a0); split_u64(w[2],  w[3],  b0);
    split_u64(w[4],  w[5],  a1); split_u64(w[6],  w[7],  b1);
    split_u64(w[8],  w[9],  a2); split_u64(w[10], w[11], b2);
    split_u64(w[12], w[13], a3); split_u64(w[14], w[15], b3);
    ull c0 = mul2(bf2f(w[0]),  Ep[0]);
    ull c1 = mul2(bf2f(w[4]),  Ep[4]);
    ull c2 = mul2(bf2f(w[8]),  Ep[8]);
    ull c3 = mul2(bf2f(w[12]), Ep[12]);
    c0 = fma2(bf2f(w[1]),  Ep[1],  c0);
    c1 = fma2(bf2f(w[5]),  Ep[5],  c1);
    c2 = fma2(bf2f(w[9]),  Ep[9],  c2);
    c3 = fma2(bf2f(w[13]), Ep[13], c3);
    c0 = fma2(bf2f(w[2]),  Ep[2],  c0);
    c1 = fma2(bf2f(w[6]),  Ep[6],  c1);
    c2 = fma2(bf2f(w[10]), Ep[10], c2);
    c3 = fma2(bf2f(w[14]), Ep[14], c3);
    c0 = fma2(bf2f(w[3]),  Ep[3],  c0);
    c1 = fma2(bf2f(w[7]),  Ep[7],  c1);
    c2 = fma2(bf2f(w[11]), Ep[11], c2);
    c3 = fma2(bf2f(w[15]), Ep[15], c3);
    ull g = add2(add2(c0, c1), add2(c2, c3));
    float lo, hi;
    unpack2(lo, hi, g);
    return lo + hi;
}

// deterministic fixed-order final reduction, run by the last block to finish
__device__ __forceinline__ void final_reduce(float* out, int B, int total, int lane) {
    __threadfence();
    int old = 0;
    if (lane == 0) old = atomicAdd(&g_count, 1);
    old = __shfl_sync(FULL_MASK, old, 0);
    if (old == total - 1) {
        __threadfence();
        double acc = 0.0;
        for (int i = lane; i < B; i += 32)
            acc += (double)((volatile float*)g_fwd)[i]
                 - (double)((volatile float*)g_gold)[i];
#pragma unroll
        for (int o = 16; o; o >>= 1)
            acc += __shfl_xor_sync(FULL_MASK, acc, o);
        if (lane == 0) {
            out[0] = (float)acc;
            g_count = 0;   // reset for next graph replay
        }
    }
}

// Blocks [0, B): one block = one batch; warp 0 forward to m, warp 1 backward
// to m; Z = sum_i alphaExp_m(i)*betaExp_m(i). The per-step state broadcast is
// bf16 (halves smem-crossbar replication bytes); E and all accumulation fp32.
// Blocks [B, B+GOLD_BLOCKS): gold-score gatherers overlapping the scan.
__global__ void __launch_bounds__(64, 8)
crf_nll_kernel(const float* __restrict__ feats,
               const float* __restrict__ trans,
               const int*   __restrict__ tags,
               const int*   __restrict__ lens,
               float* __restrict__ out,
               int B, int L)
{
    int tid  = threadIdx.x;
    int wid  = tid >> 5;
    int lane = tid & 31;
    int total = B + GOLD_BLOCKS;

    if (blockIdx.x >= (unsigned)B) {
        // ================= GOLD blocks: 8 batches each ======================
        __shared__ float sw[2];
        int gb = blockIdx.x - B;
#pragma unroll 1
        for (int i = 0; i < 8; ++i) {
            int b = gb * 8 + i;
            const float* fb = feats + (size_t)b * L * TAGS;
            const int*   tb = tags  + (size_t)b * L;
            int len = lens[b];

            float s = 0.f;
            for (int t = tid; t < len - 1; t += 64) {
                int u = tb[t], w = tb[t + 1];
                s += trans[u * TAGS + w] + fb[(t + 1) * TAGS + w];
            }
#pragma unroll
            for (int o = 16; o; o >>= 1) s += __shfl_xor_sync(FULL_MASK, s, o);
            if (lane == 0) sw[wid] = s;
            __syncthreads();
            if (tid == 0) {
                float mid = sw[0] + sw[1];
                int tag0 = tb[0];
                int tend = tb[len - 1];
                g_gold[b] = trans[START * TAGS + tag0] + fb[tag0]
                          + trans[tend * TAGS + STOP] + mid;
            }
            __syncthreads();
        }
        if (wid == 0) final_reduce(out, B, total, lane);
        return;
    }

    // ===================== SCAN blocks ======================================
    __shared__ __align__(16) uint16_t bufA[2][TAGS];   // bf16 broadcast rows
    __shared__ __align__(16) uint16_t bufB[2][TAGS];
    __shared__ __align__(16) float qout[TAGS];
    __shared__ float s_lsB;

    int b = blockIdx.x;
    const float* fb = feats + (size_t)b * L * TAGS;
    int len = lens[b];
    int m   = (len - 1) >> 1;

    if (wid == 0) {
        // FORWARD warp: alpha over feats[0..m]
        ull Ep[TAGS / 2];
#pragma unroll
        for (int k = 0; k < TAGS / 2; ++k) {
            float e0 = __expf(trans[(2 * k)     * TAGS + lane]);
            float e1 = __expf(trans[(2 * k + 1) * TAGS + lane]);
            Ep[k] = pack2(e0, e1);
        }

        float a0 = trans[START * TAGS + lane] + fb[lane];
        float mx = a0;
#pragma unroll
        for (int o = 16; o; o >>= 1) mx = fmaxf(mx, __shfl_xor_sync(FULL_MASK, mx, o));
        float p = __expf(a0 - mx);
        float lsA = mx;

        float q0 = fb[min(1, m) * TAGS + lane];
        float q1 = fb[min(2, m) * TAGS + lane];
        float q2 = fb[min(3, m) * TAGS + lane];
        float q3 = fb[min(4, m) * TAGS + lane];

        uint32_t sb = (uint32_t)__cvta_generic_to_shared(&bufA[0][0]);
        float m0 = 1.0f, rr = 1.0f, lg = 0.0f;

#pragma unroll 4
        for (int t = 1; t <= m; ++t) {
            float f = __expf(q0);
            q0 = q1; q1 = q2; q2 = q3;
            q3 = fb[min(t + 4, m) * TAGS + lane];

            int slot = t & 1;
            uint32_t base = sb + (uint32_t)slot * (TAGS * 2);
            sts16(base + lane * 2, f32_to_bf16(p));
            p = matvec32_bf16(base, Ep) * f;

            int ph = t & 3;
            if (ph == 0) {
                m0 = __shfl_sync(FULL_MASK, p, 0);
            } else if (ph == 1) {
                rr = __fdividef(1.0f, m0);
                lg = __logf(m0);
            } else if (ph == 3) {
                p *= rr;
                lsA += lg;
            }
        }

        __syncthreads();   // backward result ready in qout / s_lsB

        float v = p * qout[lane];
#pragma unroll
        for (int o = 16; o; o >>= 1) v += __shfl_xor_sync(FULL_MASK, v, o);
        float fwd = lsA + s_lsB + __logf(v);

        if (lane == 0) g_fwd[b] = fwd;
        final_reduce(out, B, total, lane);
    } else {
        // BACKWARD warp: beta over feats[m+1..len-1]
        ull Ep[TAGS / 2];
#pragma unroll
        for (int k = 0; k < TAGS / 2; ++k) {
            float e0 = __expf(trans[lane * TAGS + 2 * k]);
            float e1 = __expf(trans[lane * TAGS + 2 * k + 1]);
            Ep[k] = pack2(e0, e1);
        }

        float q = __expf(trans[lane * TAGS + STOP]);
        float lsB = 0.f;

        int steps = (len - 1) - m;
        float q0 = fb[max(len - 1, 0) * TAGS + lane];
        float q1 = fb[max(len - 2, 0) * TAGS + lane];
        float q2 = fb[max(len - 3, 0) * TAGS + lane];
        float q3 = fb[max(len - 4, 0) * TAGS + lane];

        uint32_t sb = (uint32_t)__cvta_generic_to_shared(&bufB[0][0]);
        float m0 = 1.0f, rr = 1.0f, lg = 0.0f;

#pragma unroll 4
        for (int s = 0; s < steps; ++s) {
            float f = __expf(q0);
            q0 = q1; q1 = q2; q2 = q3;
            q3 = fb[max(len - 5 - s, 0) * TAGS + lane];

            float r = q * f;
            int slot = s & 1;
            uint32_t base = sb + (uint32_t)slot * (TAGS * 2);
            sts16(base + lane * 2, f32_to_bf16(r));
            q = matvec32_bf16(base, Ep);

            int ph = s & 3;
            if (ph == 0) {
                m0 = __shfl_sync(FULL_MASK, q, 0);
            } else if (ph == 1) {
                rr = __fdividef(1.0f, m0);
                lg = __logf(m0);
            } else if (ph == 3) {
                q *= rr;
                lsB += lg;
            }
        }

        qout[lane] = q;
        if (lane == 0) s_lsB = lsB;
        __syncthreads();
        // warp 0 finishes combine + reduction participation
    }
}

extern "C" void kernel_launch(void* const* d_in, const int* in_sizes, int n_in,
                              void* d_out, int out_size)
{
    const float* feats = (const float*)d_in[0];
    const float* trans = (const float*)d_in[1];
    const int*   tags  = (const int*)d_in[2];
    const int*   lens  = (const int*)d_in[3];
    float* out = (float*)d_out;

    int B = in_sizes[3];                  // word_seq_lens: (B,)
    int L = in_sizes[2] / B;              // tags: (B, L)

    crf_nll_kernel<<<B + GOLD_BLOCKS, 64>>>(feats, trans, tags, lens, out, B, L);
}

// round 16
// speedup vs baseline: 1.2695x; 1.2695x over previous
#include <cuda_runtime.h>
#include <cuda_bf16.h>
#include <cstdint>

#define FULL_MASK 0xFFFFFFFFu
#define TAGS 32
#define START 30
#define STOP 31
#define GOLD_BLOCKS 128

__device__ float g_fwd[2048];
__device__ float g_gold[2048];
__device__ int   g_order[2048];
__device__ int   g_count = 0;

typedef unsigned long long ull;

// ---- packed fp32x2 helpers ----
__device__ __forceinline__ ull pack2(float lo, float hi) {
    ull r; asm("mov.b64 %0, {%1, %2};" : "=l"(r) : "f"(lo), "f"(hi)); return r;
}
__device__ __forceinline__ void unpack2(float& lo, float& hi, ull v) {
    asm("mov.b64 {%0, %1}, %2;" : "=f"(lo), "=f"(hi) : "l"(v));
}
__device__ __forceinline__ ull fma2(ull a, ull b, ull c) {
    ull r; asm("fma.rn.f32x2 %0, %1, %2, %3;" : "=l"(r) : "l"(a), "l"(b), "l"(c)); return r;
}
__device__ __forceinline__ ull mul2(ull a, ull b) {
    ull r; asm("mul.rn.f32x2 %0, %1, %2;" : "=l"(r) : "l"(a), "l"(b)); return r;
}
__device__ __forceinline__ ull add2(ull a, ull b) {
    ull r; asm("add.rn.f32x2 %0, %1, %2;" : "=l"(r) : "l"(a), "l"(b)); return r;
}
__device__ __forceinline__ void lds_v2u64(ull& a, ull& b, uint32_t addr) {
    asm volatile("ld.shared.v2.u64 {%0, %1}, [%2];" : "=l"(a), "=l"(b) : "r"(addr));
}

// packed matvec: 8x LDS.v2.u64 feeding 16 packed fma/mul, 7 packed adds
__device__ __forceinline__ float matvec32(uint32_t base, const ull* Ep) {
    ull c0, c1, c2, c3, c4, c5, c6, c7;
    ull qa, qb;
    lds_v2u64(qa, qb, base +   0); c0 = fma2(qb, Ep[ 1], mul2(qa, Ep[ 0]));
    lds_v2u64(qa, qb, base +  16); c1 = fma2(qb, Ep[ 3], mul2(qa, Ep[ 2]));
    lds_v2u64(qa, qb, base +  32); c2 = fma2(qb, Ep[ 5], mul2(qa, Ep[ 4]));
    lds_v2u64(qa, qb, base +  48); c3 = fma2(qb, Ep[ 7], mul2(qa, Ep[ 6]));
    lds_v2u64(qa, qb, base +  64); c4 = fma2(qb, Ep[ 9], mul2(qa, Ep[ 8]));
    lds_v2u64(qa, qb, base +  80); c5 = fma2(qb, Ep[11], mul2(qa, Ep[10]));
    lds_v2u64(qa, qb, base +  96); c6 = fma2(qb, Ep[13], mul2(qa, Ep[12]));
    lds_v2u64(qa, qb, base + 112); c7 = fma2(qb, Ep[15], mul2(qa, Ep[14]));
    ull d0 = add2(c0, c1), d1 = add2(c2, c3);
    ull d2 = add2(c4, c5), d3 = add2(c6, c7);
    ull g  = add2(add2(d0, d1), add2(d2, d3));
    float lo, hi;
    unpack2(lo, hi, g);
    return lo + hi;
}

// forward half-scan: alpha over feats[0..m]; returns lane's exp-domain comp.
__device__ __forceinline__ float fwd_scan(const float* __restrict__ fb,
                                          const float* __restrict__ trans,
                                          int m, int lane,
                                          float* bufw, uint32_t sb, float& ls_out)
{
    ull Ep[TAGS / 2];
#pragma unroll
    for (int k = 0; k < TAGS / 2; ++k) {
        float e0 = __expf(trans[(2 * k)     * TAGS + lane]);
        float e1 = __expf(trans[(2 * k + 1) * TAGS + lane]);
        Ep[k] = pack2(e0, e1);
    }
    float a0 = trans[START * TAGS + lane] + fb[lane];
    float mx = a0;
#pragma unroll
    for (int o = 16; o; o >>= 1) mx = fmaxf(mx, __shfl_xor_sync(FULL_MASK, mx, o));
    float p = __expf(a0 - mx);
    float ls = mx;

    float q0 = fb[min(1, m) * TAGS + lane];
    float q1 = fb[min(2, m) * TAGS + lane];
    float q2 = fb[min(3, m) * TAGS + lane];
    float q3 = fb[min(4, m) * TAGS + lane];

    float m0 = 1.0f, rr = 1.0f, lg = 0.0f;
#pragma unroll 4
    for (int t = 1; t <= m; ++t) {
        float f = __expf(q0);
        q0 = q1; q1 = q2; q2 = q3;
        q3 = fb[min(t + 4, m) * TAGS + lane];

        int slot = t & 1;
        bufw[slot * TAGS + lane] = p;
        __syncwarp();
        p = matvec32(sb + slot * (TAGS * 4), Ep) * f;

        int ph = t & 3;
        if (ph == 0)      { m0 = __shfl_sync(FULL_MASK, p, 0); }
        else if (ph == 1) { rr = __fdividef(1.0f, m0); lg = __logf(m0); }
        else if (ph == 3) { p *= rr; ls += lg; }
    }
    ls_out = ls;
    return p;
}

// backward half-scan: beta over feats[m+1..len-1]
__device__ __forceinline__ float bwd_scan(const float* __restrict__ fb,
                                          const float* __restrict__ trans,
                                          int len, int m, int lane,
                                          float* bufw, uint32_t sb, float& ls_out)
{
    ull Ep[TAGS / 2];
#pragma unroll
    for (int k = 0; k < TAGS / 2; ++k) {
        float e0 = __expf(trans[lane * TAGS + 2 * k]);
        float e1 = __expf(trans[lane * TAGS + 2 * k + 1]);
        Ep[k] = pack2(e0, e1);
    }
    float q = __expf(trans[lane * TAGS + STOP]);
    float ls = 0.f;

    int steps = (len - 1) - m;
    float q0 = fb[max(len - 1, 0) * TAGS + lane];
    float q1 = fb[max(len - 2, 0) * TAGS + lane];
    float q2 = fb[max(len - 3, 0) * TAGS + lane];
    float q3 = fb[max(len - 4, 0) * TAGS + lane];

    float m0 = 1.0f, rr = 1.0f, lg = 0.0f;
#pragma unroll 4
    for (int s = 0; s < steps; ++s) {
        float f = __expf(q0);
        q0 = q1; q1 = q2; q2 = q3;
        q3 = fb[max(len - 5 - s, 0) * TAGS + lane];

        float r = q * f;
        int slot = s & 1;
        bufw[slot * TAGS + lane] = r;
        __syncwarp();
        q = matvec32(sb + slot * (TAGS * 4), Ep);

        int ph = s & 3;
        if (ph == 0)      { m0 = __shfl_sync(FULL_MASK, q, 0); }
        else if (ph == 1) { rr = __fdividef(1.0f, m0); lg = __logf(m0); }
        else if (ph == 3) { q *= rr; ls += lg; }
    }
    ls_out = ls;
    return q;
}

// deterministic fixed-order final reduction by the last block to finish
__device__ __forceinline__ void final_reduce(float* out, int B, int total, int lane) {
    __threadfence();
    int old = 0;
    if (lane == 0) old = atomicAdd(&g_count, 1);
    old = __shfl_sync(FULL_MASK, old, 0);
    if (old == total - 1) {
        __threadfence();
        double acc = 0.0;
        for (int i = lane; i < B; i += 32)
            acc += (double)((volatile float*)g_fwd)[i]
                 - (double)((volatile float*)g_gold)[i];
#pragma unroll
        for (int o = 16; o; o >>= 1)
            acc += __shfl_xor_sync(FULL_MASK, acc, o);
        if (lane == 0) {
            out[0] = (float)acc;
            g_count = 0;   // reset for next graph replay
        }
    }
}

// counting sort by descending length (512 threads; warp-0 bucket scan)
__global__ void sort_kernel(const int* __restrict__ lens, int B, int L)
{
    __shared__ int hist[520];
    __shared__ int offs[520];
    int tid = threadIdx.x;
    int lane = tid & 31;
    int nb = L + 1;
    if (nb > 520) {
        for (int b = tid; b < B; b += blockDim.x) g_order[b] = b;
        return;
    }
    for (int i = tid; i < nb; i += blockDim.x) hist[i] = 0;
    __syncthreads();
    for (int b = tid; b < B; b += blockDim.x)
        atomicAdd(&hist[L - lens[b]], 1);           // key = desc length
    __syncthreads();
    if (tid < 32) {
        int run = 0;
        for (int c = 0; c < nb; c += 32) {
            int v = (c + lane < nb) ? hist[c + lane] : 0;
            int s = v;
#pragma unroll
            for (int o = 1; o < 32; o <<= 1) {
                int u = __shfl_up_sync(FULL_MASK, s, o);
                if (lane >= o) s += u;
            }
            if (c + lane < nb) offs[c + lane] = run + s - v;   // exclusive
            run += __shfl_sync(FULL_MASK, s, 31);
        }
    }
    __syncthreads();
    for (int b = tid; b < B; b += blockDim.x) {
        int pos = atomicAdd(&offs[L - lens[b]], 1);
        g_order[pos] = b;
    }
}

// Blocks [0, npair): pair (X=order[r], Y=order[B-1-r]); lenX+lenY ~ const, so
// each warp runs ~ (lenX+lenY)/2 steps -> all scan warps finish together (no
// drain tail). Warp0: fwd(X)+bwd(Y); warp1: bwd(X)+fwd(Y); combine per batch.
// Blocks [npair, npair+GOLD_BLOCKS): gold gatherers overlapping the scan.
__global__ void __launch_bounds__(64, 8)
crf_nll_kernel(const float* __restrict__ feats,
               const float* __restrict__ trans,
               const int*   __restrict__ tags,
               const int*   __restrict__ lens,
               float* __restrict__ out,
               int B, int L)
{
    int tid  = threadIdx.x;
    int wid  = tid >> 5;
    int lane = tid & 31;
    int npair = (B + 1) >> 1;
    int total = npair + GOLD_BLOCKS;

    if (blockIdx.x >= (unsigned)npair) {
        // ================= GOLD blocks ======================================
        __shared__ float sw[2];
        int gb = blockIdx.x - npair;
#pragma unroll 1
        for (int b = gb; b < B; b += GOLD_BLOCKS) {
            const float* fb = feats + (size_t)b * L * TAGS;
            const int*   tb = tags  + (size_t)b * L;
            int len = lens[b];

            float s = 0.f;
            for (int t = tid; t < len - 1; t += 64) {
                int u = tb[t], w = tb[t + 1];
                s += trans[u * TAGS + w] + fb[(t + 1) * TAGS + w];
            }
#pragma unroll
            for (int o = 16; o; o >>= 1) s += __shfl_xor_sync(FULL_MASK, s, o);
            if (lane == 0) sw[wid] = s;
            __syncthreads();
            if (tid == 0) {
                float mid = sw[0] + sw[1];
                int tag0 = tb[0];
                int tend = tb[len - 1];
                g_gold[b] = trans[START * TAGS + tag0] + fb[tag0]
                          + trans[tend * TAGS + STOP] + mid;
            }
            __syncthreads();
        }
        if (wid == 0) final_reduce(out, B, total, lane);
        return;
    }

    // ===================== SCAN pair blocks =================================
    __shared__ __align__(16) float ping[2][2][TAGS];   // [warp][slot][tag]
    __shared__ __align__(16) float alphaS[2][TAGS];    // [0]=X, [1]=Y
    __shared__ __align__(16) float betaS[2][TAGS];
    __shared__ float lsA[2], lsB[2];

    int r  = blockIdx.x;
    int bX = g_order[r];
    int bY = g_order[B - 1 - r];
    const float* fX = feats + (size_t)bX * L * TAGS;
    const float* fY = feats + (size_t)bY * L * TAGS;
    int lenX = lens[bX], lenY = lens[bY];
    int mX = (lenX - 1) >> 1, mY = (lenY - 1) >> 1;

    float* bufw = &ping[wid][0][0];
    uint32_t sb = (uint32_t)__cvta_generic_to_shared(bufw);

    float ls;
    if (wid == 0) {
        float p = fwd_scan(fX, trans, mX, lane, bufw, sb, ls);
        alphaS[0][lane] = p;  if (lane == 0) lsA[0] = ls;
        float q = bwd_scan(fY, trans, lenY, mY, lane, bufw, sb, ls);
        betaS[1][lane] = q;   if (lane == 0) lsB[1] = ls;
    } else {
        float q = bwd_scan(fX, trans, lenX, mX, lane, bufw, sb, ls);
        betaS[0][lane] = q;   if (lane == 0) lsB[0] = ls;
        float p = fwd_scan(fY, trans, mY, lane, bufw, sb, ls);
        alphaS[1][lane] = p;  if (lane == 0) lsA[1] = ls;
    }
    __syncthreads();

    // warp w combines its batch (w=0 -> X, w=1 -> Y)
    int bb = (wid == 0) ? bX : bY;
    float v = alphaS[wid][lane] * betaS[wid][lane];
#pragma unroll
    for (int o = 16; o; o >>= 1) v += __shfl_xor_sync(FULL_MASK, v, o);
    float fwd = lsA[wid] + lsB[wid] + __logf(v);
    if (lane == 0) g_fwd[bb] = fwd;

    __syncthreads();
    if (wid == 0) final_reduce(out, B, total, lane);
}

extern "C" void kernel_launch(void* const* d_in, const int* in_sizes, int n_in,
                              void* d_out, int out_size)
{
    const float* feats = (const float*)d_in[0];
    const float* trans = (const float*)d_in[1];
    const int*   tags  = (const int*)d_in[2];
    const int*   lens  = (const int*)d_in[3];
    float* out = (float*)d_out;

    int B = in_sizes[3];                  // word_seq_lens: (B,)
    int L = in_sizes[2] / B;              // tags: (B, L)

    int npair = (B + 1) >> 1;
    sort_kernel<<<1, 512>>>(lens, B, L);
    crf_nll_kernel<<<npair + GOLD_BLOCKS, 64>>>(feats, trans, tags, lens, out, B, L);
}

// round 17
// speedup vs baseline: 1.3546x; 1.0670x over previous
#include <cuda_runtime.h>
#include <cuda_bf16.h>
#include <cstdint>

#define FULL_MASK 0xFFFFFFFFu
#define TAGS 32
#define START 30
#define STOP 31
#define GOLD_BLOCKS 128

__device__ float g_fwd[2048];
__device__ float g_gold[2048];
__device__ int   g_order[2048];
__device__ int   g_count = 0;

typedef unsigned long long ull;

// ---- bf16x2 helpers ----
__device__ __forceinline__ uint32_t bfpack(float lo, float hi) {
    // cvt.rn.bf16x2.f32 d, a, b -> d = {hi=a, lo=b}
    uint32_t r; asm("cvt.rn.bf16x2.f32 %0, %1, %2;" : "=r"(r) : "f"(hi), "f"(lo)); return r;
}
__device__ __forceinline__ uint16_t f2bf(float f) {
    uint16_t h; asm("cvt.rn.bf16.f32 %0, %1;" : "=h"(h) : "f"(f)); return h;
}
__device__ __forceinline__ uint32_t bffma(uint32_t a, uint32_t b, uint32_t c) {
    uint32_t r; asm("fma.rn.bf16x2 %0, %1, %2, %3;" : "=r"(r) : "r"(a), "r"(b), "r"(c)); return r;
}
__device__ __forceinline__ uint32_t bfadd(uint32_t a, uint32_t b) {
    uint32_t r; asm("add.rn.bf16x2 %0, %1, %2;" : "=r"(r) : "r"(a), "r"(b)); return r;
}
__device__ __forceinline__ void lds_v2u64(ull& a, ull& b, uint32_t addr) {
    asm volatile("ld.shared.v2.u64 {%0, %1}, [%2];" : "=l"(a), "=l"(b) : "r"(addr));
}
__device__ __forceinline__ void sts16(uint32_t addr, uint16_t v) {
    asm volatile("st.shared.b16 [%0], %1;" :: "r"(addr), "h"(v));
}
__device__ __forceinline__ void split_u64(uint32_t& lo, uint32_t& hi, ull v) {
    asm("mov.b64 {%0, %1}, %2;" : "=r"(lo), "=r"(hi) : "l"(v));
}

// bf16 broadcast matvec: p (32 x bf16 = 64B) read with 4x LDS.v2.u64,
// dot done natively in bf16x2 HFMA2 (no unpack on the load->fma edge).
__device__ __forceinline__ float matvec32_bf16(uint32_t base, const uint32_t* Eb) {
    ull x0, y0, x1, y1;
    uint32_t w[16];
    lds_v2u64(x0, y0, base +  0);
    lds_v2u64(x1, y1, base + 16);
    split_u64(w[0], w[1], x0);  split_u64(w[2], w[3], y0);
    split_u64(w[4], w[5], x1);  split_u64(w[6], w[7], y1);
    lds_v2u64(x0, y0, base + 32);
    lds_v2u64(x1, y1, base + 48);
    split_u64(w[8],  w[9],  x0); split_u64(w[10], w[11], y0);
    split_u64(w[12], w[13], x1); split_u64(w[14], w[15], y1);

    uint32_t a0 = 0, a1 = 0, a2 = 0, a3 = 0;
#pragma unroll
    for (int k = 0; k < 4; ++k) {
        a0 = bffma(w[4 * k + 0], Eb[4 * k + 0], a0);
        a1 = bffma(w[4 * k + 1], Eb[4 * k + 1], a1);
        a2 = bffma(w[4 * k + 2], Eb[4 * k + 2], a2);
        a3 = bffma(w[4 * k + 3], Eb[4 * k + 3], a3);
    }
    uint32_t s0 = bfadd(a0, a1);
    uint32_t s1 = bfadd(a2, a3);
    // bf16 is truncated fp32: unpack via shift/mask
    float f0 = __uint_as_float(s0 << 16);
    float f1 = __uint_as_float(s0 & 0xFFFF0000u);
    float f2 = __uint_as_float(s1 << 16);
    float f3 = __uint_as_float(s1 & 0xFFFF0000u);
    return (f0 + f1) + (f2 + f3);
}

// forward half-scan: alpha over feats[0..m]
__device__ __forceinline__ float fwd_scan(const float* __restrict__ fb,
                                          const float* __restrict__ trans,
                                          int m, int lane, uint32_t sb, float& ls_out)
{
    uint32_t Eb[16];
#pragma unroll
    for (int k = 0; k < 16; ++k)
        Eb[k] = bfpack(__expf(trans[(2 * k) * TAGS + lane]),
                       __expf(trans[(2 * k + 1) * TAGS + lane]));

    float a0 = trans[START * TAGS + lane] + fb[lane];
    float mx = a0;
#pragma unroll
    for (int o = 16; o; o >>= 1) mx = fmaxf(mx, __shfl_xor_sync(FULL_MASK, mx, o));
    float p = __expf(a0 - mx);
    float ls = mx;

    float q0 = fb[min(1, m) * TAGS + lane];
    float q1 = fb[min(2, m) * TAGS + lane];
    float q2 = fb[min(3, m) * TAGS + lane];
    float q3 = fb[min(4, m) * TAGS + lane];

    float m0 = 1.0f, rr = 1.0f, lg = 0.0f;
#pragma unroll 4
    for (int t = 1; t <= m; ++t) {
        float f = __expf(q0);
        q0 = q1; q1 = q2; q2 = q3;
        q3 = fb[min(t + 4, m) * TAGS + lane];

        uint32_t base = sb + (uint32_t)(t & 1) * (TAGS * 2);
        sts16(base + lane * 2, f2bf(p));
        p = matvec32_bf16(base, Eb) * f;

        int ph = t & 3;
        if (ph == 0)      { m0 = __shfl_sync(FULL_MASK, p, 0); }
        else if (ph == 1) { rr = __fdividef(1.0f, m0); lg = __logf(m0); }
        else if (ph == 3) { p *= rr; ls += lg; }
    }
    ls_out = ls;
    return p;
}

// backward half-scan: beta over feats[m+1..len-1]
__device__ __forceinline__ float bwd_scan(const float* __restrict__ fb,
                                          const float* __restrict__ trans,
                                          int len, int m, int lane, uint32_t sb, float& ls_out)
{
    uint32_t Eb[16];
#pragma unroll
    for (int k = 0; k < 16; ++k)
        Eb[k] = bfpack(__expf(trans[lane * TAGS + 2 * k]),
                       __expf(trans[lane * TAGS + 2 * k + 1]));

    float q = __expf(trans[lane * TAGS + STOP]);
    float ls = 0.f;

    int steps = (len - 1) - m;
    float q0 = fb[max(len - 1, 0) * TAGS + lane];
    float q1 = fb[max(len - 2, 0) * TAGS + lane];
    float q2 = fb[max(len - 3, 0) * TAGS + lane];
    float q3 = fb[max(len - 4, 0) * TAGS + lane];

    float m0 = 1.0f, rr = 1.0f, lg = 0.0f;
#pragma unroll 4
    for (int s = 0; s < steps; ++s) {
        float f = __expf(q0);
        q0 = q1; q1 = q2; q2 = q3;
        q3 = fb[max(len - 5 - s, 0) * TAGS + lane];

        float r = q * f;
        uint32_t base = sb + (uint32_t)(s & 1) * (TAGS * 2);
        sts16(base + lane * 2, f2bf(r));
        q = matvec32_bf16(base, Eb);

        int ph = s & 3;
        if (ph == 0)      { m0 = __shfl_sync(FULL_MASK, q, 0); }
        else if (ph == 1) { rr = __fdividef(1.0f, m0); lg = __logf(m0); }
        else if (ph == 3) { q *= rr; ls += lg; }
    }
    ls_out = ls;
    return q;
}

// deterministic fixed-order final reduction by the last block to finish
__device__ __forceinline__ void final_reduce(float* out, int B, int total, int lane) {
    __threadfence();
    int old = 0;
    if (lane == 0) old = atomicAdd(&g_count, 1);
    old = __shfl_sync(FULL_MASK, old, 0);
    if (old == total - 1) {
        __threadfence();
        double acc = 0.0;
        for (int i = lane; i < B; i += 32)
            acc += (double)((volatile float*)g_fwd)[i]
                 - (double)((volatile float*)g_gold)[i];
#pragma unroll
        for (int o = 16; o; o >>= 1)
            acc += __shfl_xor_sync(FULL_MASK, acc, o);
        if (lane == 0) {
            out[0] = (float)acc;
            g_count = 0;   // reset for next graph replay
        }
    }
}

// counting sort by descending length (1024 threads; warp-0 bucket scan)
__global__ void sort_kernel(const int* __restrict__ lens, int B, int L)
{
    __shared__ int hist[520];
    __shared__ int offs[520];
    int tid = threadIdx.x;
    int lane = tid & 31;
    int nb = L + 1;
    if (nb > 520) {
        for (int b = tid; b < B; b += blockDim.x) g_order[b] = b;
        return;
    }
    for (int i = tid; i < nb; i += blockDim.x) hist[i] = 0;
    __syncthreads();
    for (int b = tid; b < B; b += blockDim.x)
        atomicAdd(&hist[L - lens[b]], 1);           // key = desc length
    __syncthreads();
    if (tid < 32) {
        int run = 0;
        for (int c = 0; c < nb; c += 32) {
            int v = (c + lane < nb) ? hist[c + lane] : 0;
            int s = v;
#pragma unroll
            for (int o = 1; o < 32; o <<= 1) {
                int u = __shfl_up_sync(FULL_MASK, s, o);
                if (lane >= o) s += u;
            }
            if (c + lane < nb) offs[c + lane] = run + s - v;   // exclusive
            run += __shfl_sync(FULL_MASK, s, 31);
        }
    }
    __syncthreads();
    for (int b = tid; b < B; b += blockDim.x) {
        int pos = atomicAdd(&offs[L - lens[b]], 1);
        g_order[pos] = b;
    }
}

// Blocks [0, npair): pair (X=order[r], Y=order[B-1-r]); lenX+lenY ~ const ->
// all scan warps finish together. Warp0: fwd(X)+bwd(Y); warp1: bwd(X)+fwd(Y).
// Blocks [npair, npair+GOLD_BLOCKS): gold gatherers overlapping the scan.
__global__ void __launch_bounds__(64, 8)
crf_nll_kernel(const float* __restrict__ feats,
               const float* __restrict__ trans,
               const int*   __restrict__ tags,
               const int*   __restrict__ lens,
               float* __restrict__ out,
               int B, int L)
{
    int tid  = threadIdx.x;
    int wid  = tid >> 5;
    int lane = tid & 31;
    int npair = (B + 1) >> 1;
    int total = npair + GOLD_BLOCKS;

    if (blockIdx.x >= (unsigned)npair) {
        // ================= GOLD blocks ======================================
        __shared__ float sw[2];
        int gb = blockIdx.x - npair;
#pragma unroll 1
        for (int b = gb; b < B; b += GOLD_BLOCKS) {
            const float* fb = feats + (size_t)b * L * TAGS;
            const int*   tb = tags  + (size_t)b * L;
            int len = lens[b];

            float s = 0.f;
            for (int t = tid; t < len - 1; t += 64) {
                int u = tb[t], w = tb[t + 1];
                s += trans[u * TAGS + w] + fb[(t + 1) * TAGS + w];
            }
#pragma unroll
            for (int o = 16; o; o >>= 1) s += __shfl_xor_sync(FULL_MASK, s, o);
            if (lane == 0) sw[wid] = s;
            __syncthreads();
            if (tid == 0) {
                float mid = sw[0] + sw[1];
                int tag0 = tb[0];
                int tend = tb[len - 1];
                g_gold[b] = trans[START * TAGS + tag0] + fb[tag0]
                          + trans[tend * TAGS + STOP] + mid;
            }
            __syncthreads();
        }
        if (wid == 0) final_reduce(out, B, total, lane);
        return;
    }

    // ===================== SCAN pair blocks =================================
    __shared__ __align__(16) uint16_t ping[2][2][TAGS];   // [warp][slot][tag] bf16
    __shared__ __align__(16) float alphaS[2][TAGS];       // [0]=X, [1]=Y
    __shared__ __align__(16) float betaS[2][TAGS];
    __shared__ float lsA[2], lsB[2];

    int r  = blockIdx.x;
    int bX = g_order[r];
    int bY = g_order[B - 1 - r];
    const float* fX = feats + (size_t)bX * L * TAGS;
    const float* fY = feats + (size_t)bY * L * TAGS;
    int lenX = lens[bX], lenY = lens[bY];
    int mX = (lenX - 1) >> 1, mY = (lenY - 1) >> 1;

    uint32_t sb = (uint32_t)__cvta_generic_to_shared(&ping[wid][0][0]);

    float ls;
    if (wid == 0) {
        float p = fwd_scan(fX, trans, mX, lane, sb, ls);
        alphaS[0][lane] = p;  if (lane == 0) lsA[0] = ls;
        float q = bwd_scan(fY, trans, lenY, mY, lane, sb, ls);
        betaS[1][lane] = q;   if (lane == 0) lsB[1] = ls;
    } else {
        float q = bwd_scan(fX, trans, lenX, mX, lane, sb, ls);
        betaS[0][lane] = q;   if (lane == 0) lsB[0] = ls;
        float p = fwd_scan(fY, trans, mY, lane, sb, ls);
        alphaS[1][lane] = p;  if (lane == 0) lsA[1] = ls;
    }
    __syncthreads();

    // warp w combines its batch (w=0 -> X, w=1 -> Y)
    int bb = (wid == 0) ? bX : bY;
    float v = alphaS[wid][lane] * betaS[wid][lane];
#pragma unroll
    for (int o = 16; o; o >>= 1) v += __shfl_xor_sync(FULL_MASK, v, o);
    float fwd = lsA[wid] + lsB[wid] + __logf(v);
    if (lane == 0) g_fwd[bb] = fwd;

    __syncthreads();
    if (wid == 0) final_reduce(out, B, total, lane);
}

extern "C" void kernel_launch(void* const* d_in, const int* in_sizes, int n_in,
                              void* d_out, int out_size)
{
    const float* feats = (const float*)d_in[0];
    const float* trans = (const float*)d_in[1];
    const int*   tags  = (const int*)d_in[2];
    const int*   lens  = (const int*)d_in[3];
    float* out = (float*)d_out;

    int B = in_sizes[3];                  // word_seq_lens: (B,)
    int L = in_sizes[2] / B;              // tags: (B, L)

    int npair = (B + 1) >> 1;
    sort_kernel<<<1, 1024>>>(lens, B, L);
    crf_nll_kernel<<<npair + GOLD_BLOCKS, 64>>>(feats, trans, tags, lens, out, B, L);
}